// round 11
// baseline (speedup 1.0000x reference)
#include <cuda_runtime.h>
#include <cstdint>

// out[b,c] = dot(x[b,c,:HW], weight[c,:HW]) + bias[c]
// B = 512, C = 512, HW = 784 (float32). HBM-streaming bound, traffic minimal
// (828 MB). R11 = R10's aligned 2-row-pair blocks + 256-bit loads (LDG.E.256,
// sm_100+): half the LDG instructions, double bytes-in-flight per load.
// Pair window = 6272 B = 49 x 128B lines (128B-aligned); all rows 32B-aligned;
// v8 index j<98 / j>=98 split never straddles the row boundary.

#define B_DIM 512
#define C_DIM 512
#define HW_DIM 784
#define HW_VEC8 (HW_DIM / 8)          // 98 v8-chunks per row
#define PAIR_VEC8 (2 * HW_VEC8)       // 196 v8-chunks per row-pair
#define TOTAL_ROWS (B_DIM * C_DIM)    // 262144

// 256-bit streaming load (evict-first): 8 x b32
__device__ __forceinline__ void ldg256_cs(const float* p, uint32_t r[8]) {
    asm volatile(
        "ld.global.cs.v8.b32 {%0,%1,%2,%3,%4,%5,%6,%7}, [%8];"
        : "=r"(r[0]), "=r"(r[1]), "=r"(r[2]), "=r"(r[3]),
          "=r"(r[4]), "=r"(r[5]), "=r"(r[6]), "=r"(r[7])
        : "l"(p));
}

// 256-bit read-only load (default caching, weight stays L2-resident)
__device__ __forceinline__ void ldg256_nc(const float* p, uint32_t r[8]) {
    asm volatile(
        "ld.global.nc.v8.b32 {%0,%1,%2,%3,%4,%5,%6,%7}, [%8];"
        : "=r"(r[0]), "=r"(r[1]), "=r"(r[2]), "=r"(r[3]),
          "=r"(r[4]), "=r"(r[5]), "=r"(r[6]), "=r"(r[7])
        : "l"(p));
}

__global__ __launch_bounds__(64, 32) void scalar_mapping_kernel(
    const float* __restrict__ x,
    const float* __restrict__ weight,
    const float* __restrict__ bias,
    float* __restrict__ out)
{
    __shared__ float part[4];   // {w0.s0, w0.s1, w1.s0, w1.s1}

    const int tid  = threadIdx.x;        // 0..63
    const int lane = tid & 31;
    const int wid  = tid >> 5;           // 0 or 1

    const int r0 = blockIdx.x * 2;       // even row
    const int r1 = r0 + 1;
    const int c0 = r0 & (C_DIM - 1);     // even -> c1 = c0+1 never wraps
    const int c1 = c0 + 1;

    const float* __restrict__ xp = x + (size_t)r0 * HW_DIM;        // 128B-aligned
    const float* __restrict__ w0 = weight + (size_t)c0 * HW_DIM;   // 128B-aligned
    const float* __restrict__ w1 = weight + (size_t)c1 * HW_DIM;   // 32B-aligned

    float s0 = 0.0f, s1 = 0.0f;

    // 196 v8-chunks over 64 threads: 3 full iterations + partial (tid < 4).
    #pragma unroll
    for (int i = 0; i < 4; ++i) {
        const int j = tid + i * 64;      // v8 index within the pair window
        if (j < PAIR_VEC8) {
            uint32_t xv[8], wv[8];
            ldg256_cs(xp + j * 8, xv);
            if (j < HW_VEC8) {
                ldg256_nc(w0 + j * 8, wv);
                #pragma unroll
                for (int k = 0; k < 8; ++k)
                    s0 = fmaf(__uint_as_float(xv[k]), __uint_as_float(wv[k]), s0);
            } else {
                ldg256_nc(w1 + (j - HW_VEC8) * 8, wv);
                #pragma unroll
                for (int k = 0; k < 8; ++k)
                    s1 = fmaf(__uint_as_float(xv[k]), __uint_as_float(wv[k]), s1);
            }
        }
    }

    // Warp-level butterfly reduce of both accumulators.
    #pragma unroll
    for (int off = 16; off > 0; off >>= 1) {
        s0 += __shfl_xor_sync(0xFFFFFFFFu, s0, off);
        s1 += __shfl_xor_sync(0xFFFFFFFFu, s1, off);
    }

    if (lane == 0) {
        part[wid * 2 + 0] = s0;
        part[wid * 2 + 1] = s1;
    }
    __syncthreads();

    if (tid == 0)
        out[r0] = part[0] + part[2] + __ldg(&bias[c0]);
    else if (tid == 1)
        out[r1] = part[1] + part[3] + __ldg(&bias[c1]);
}

extern "C" void kernel_launch(void* const* d_in, const int* in_sizes, int n_in,
                              void* d_out, int out_size)
{
    const float* x      = (const float*)d_in[0];
    const float* weight = (const float*)d_in[1];
    const float* bias   = (const float*)d_in[2];
    float* out          = (float*)d_out;

    // One 2-row pair per 64-thread block -> 131072 blocks in row order.
    const int blocks = TOTAL_ROWS / 2;

    scalar_mapping_kernel<<<blocks, 64>>>(x, weight, bias, out);
}

// round 12
// speedup vs baseline: 1.0353x; 1.0353x over previous
#include <cuda_runtime.h>
#include <cstdint>

// out[b,c] = dot(x[b,c,:HW], weight[c,:HW]) + bias[c]
// B = 512, C = 512, HW = 784 (float32). HBM-streaming bound, traffic minimal
// (828 MB). R12 = R10 (aligned 2-row-pair 64-thr blocks, float4 loads) with:
//  - x loaded via ld.global.cg (L1 BYPASS, L2-cached): x has zero reuse, so
//    keep it out of L1 and leave L1 capacity + wavefronts to weight (which
//    recurs on the same SM every 256 blocks and hits at ~39cyc instead of L2).
//  - tail peeled: 6 predicate-free full iterations, front-batched loads.
//  - fused STG.64 output store.

#define B_DIM 512
#define C_DIM 512
#define HW_DIM 784
#define HW_VEC4 (HW_DIM / 4)          // 196 float4 per row
#define PAIR_VEC4 (2 * HW_VEC4)       // 392 float4 per row-pair
#define TOTAL_ROWS (B_DIM * C_DIM)    // 262144

// 128-bit load, L1-bypass (cache-global: L2 only)
__device__ __forceinline__ float4 ldg128_cg(const float4* p) {
    float4 v;
    asm volatile("ld.global.cg.v4.f32 {%0,%1,%2,%3}, [%4];"
                 : "=f"(v.x), "=f"(v.y), "=f"(v.z), "=f"(v.w)
                 : "l"(p));
    return v;
}

__global__ __launch_bounds__(64, 32) void scalar_mapping_kernel(
    const float* __restrict__ x,
    const float* __restrict__ weight,
    const float* __restrict__ bias,
    float* __restrict__ out)
{
    __shared__ float part[4];   // {w0.s0, w0.s1, w1.s0, w1.s1}

    const int tid  = threadIdx.x;        // 0..63
    const int lane = tid & 31;
    const int wid  = tid >> 5;           // 0 or 1

    const int r0 = blockIdx.x * 2;       // even row
    const int c0 = r0 & (C_DIM - 1);     // even -> c1 = c0+1 never wraps
    const int c1 = c0 + 1;

    // Contiguous, 128B-aligned 2-row window of x (6272 B = 49 lines).
    const float4* __restrict__ xr =
        reinterpret_cast<const float4*>(x + (size_t)r0 * HW_DIM);
    const float4* __restrict__ w0 =
        reinterpret_cast<const float4*>(weight + (size_t)c0 * HW_DIM);
    const float4* __restrict__ w1 =
        reinterpret_cast<const float4*>(weight + (size_t)c1 * HW_DIM);

    float s0 = 0.0f, s1 = 0.0f;

    // 6 full iterations: f = tid + 64*i, f in [0, 384) -- no predicate.
    #pragma unroll
    for (int i = 0; i < 6; ++i) {
        const int f = tid + i * 64;
        const float4 xv = ldg128_cg(&xr[f]);       // DRAM stream, L1-bypassed
        if (f < HW_VEC4) {
            const float4 wv = __ldg(&w0[f]);       // L1-resident weight
            s0 = fmaf(xv.x, wv.x, s0);
            s0 = fmaf(xv.y, wv.y, s0);
            s0 = fmaf(xv.z, wv.z, s0);
            s0 = fmaf(xv.w, wv.w, s0);
        } else {
            const float4 wv = __ldg(&w1[f - HW_VEC4]);
            s1 = fmaf(xv.x, wv.x, s1);
            s1 = fmaf(xv.y, wv.y, s1);
            s1 = fmaf(xv.z, wv.z, s1);
            s1 = fmaf(xv.w, wv.w, s1);
        }
    }
    // Peeled tail: f = 384 + tid, valid for tid < 8 (all in row 1).
    if (tid < 8) {
        const int f = 384 + tid;
        const float4 xv = ldg128_cg(&xr[f]);
        const float4 wv = __ldg(&w1[f - HW_VEC4]);
        s1 = fmaf(xv.x, wv.x, s1);
        s1 = fmaf(xv.y, wv.y, s1);
        s1 = fmaf(xv.z, wv.z, s1);
        s1 = fmaf(xv.w, wv.w, s1);
    }

    // Warp-level butterfly reduce of both accumulators.
    #pragma unroll
    for (int off = 16; off > 0; off >>= 1) {
        s0 += __shfl_xor_sync(0xFFFFFFFFu, s0, off);
        s1 += __shfl_xor_sync(0xFFFFFFFFu, s1, off);
    }

    if (lane == 0) {
        part[wid * 2 + 0] = s0;
        part[wid * 2 + 1] = s1;
    }
    __syncthreads();

    if (tid == 0) {
        float2 o;
        o.x = part[0] + part[2] + __ldg(&bias[c0]);
        o.y = part[1] + part[3] + __ldg(&bias[c1]);
        *reinterpret_cast<float2*>(&out[r0]) = o;   // out is 8B-aligned at even rows
    }
}

extern "C" void kernel_launch(void* const* d_in, const int* in_sizes, int n_in,
                              void* d_out, int out_size)
{
    const float* x      = (const float*)d_in[0];
    const float* weight = (const float*)d_in[1];
    const float* bias   = (const float*)d_in[2];
    float* out          = (float*)d_out;

    // One 2-row pair per 64-thread block -> 131072 blocks in row order.
    const int blocks = TOTAL_ROWS / 2;

    scalar_mapping_kernel<<<blocks, 64>>>(x, weight, bias, out);
}